// round 2
// baseline (speedup 1.0000x reference)
#include <cuda_runtime.h>
#include <cstddef>

// ---------------------------------------------------------------------------
// Compile-time constants: orthonormal DCT-II matrix and inverse quant table.
// All fold to FP32 immediates (FFMA-imm form, rt_SMSP=1 on sm_103a).
// ---------------------------------------------------------------------------
__device__ __host__ constexpr float cospi16(int m) {
    constexpr float t[9] = {
        1.0f,
        0.9807852804032304f, 0.9238795325112867f, 0.8314696123025452f,
        0.7071067811865476f, 0.5555702330196022f, 0.3826834323650898f,
        0.1950903220161283f, 0.0f};
    m %= 32; if (m < 0) m += 32;
    if (m > 16) m = 32 - m;
    return (m <= 8) ? t[m] : -t[16 - m];
}

// C[k][n] = f_k * cos(pi*(2n+1)*k/16)
__device__ __host__ constexpr float dctc(int k, int n) {
    return (k == 0 ? 0.3535533905932738f : 0.5f) * cospi16((2 * n + 1) * k);
}

// 1 / (lum[k][l] / 100) = 100 / lum[k][l]
__device__ __host__ constexpr float invq(int k, int l) {
    constexpr int lum[8][8] = {
        {16, 11, 10, 16, 24, 40, 51, 61},
        {12, 12, 14, 19, 26, 58, 60, 55},
        {14, 13, 16, 24, 40, 57, 69, 56},
        {14, 17, 22, 29, 51, 87, 80, 62},
        {18, 22, 37, 56, 68, 109, 103, 77},
        {24, 36, 55, 64, 81, 104, 113, 92},
        {49, 64, 78, 87, 103, 121, 120, 101},
        {72, 92, 95, 98, 112, 100, 103, 99}};
    return 100.0f / (float)lum[k][l];
}

// ---------------------------------------------------------------------------
// 8 threads per 8x8 block; 256-thread CTA handles a strip of 32 blocks
// (one h-row, 32 consecutive w-blocks).
//
// Stage 1: thread (r, wblk) loads row r of block wblk (2x LDG.128; a warp's
//          32 lanes cover 512B contiguous per LDG), does the 8-pt row DCT,
//          writes results to smem with odd stride 65 (conflict-free).
// Stage 2: thread (l, wblk) gathers column l across the 8 rows (conflict-free:
//          (wblk*65 + r*8 + l) % 32 is distinct across lanes), does the 8-pt
//          column DCT, quantizes, and stores 8 coalesced STG.32.
//
// The reference's (x - 128) shift is linear: it only shifts the 2D DC
// coefficient by 128*8 = 1024, folded in before quantization.
// ---------------------------------------------------------------------------
__global__ __launch_bounds__(256)
void jpeg_dctq_kernel(const float* __restrict__ img,
                      const float* __restrict__ qf,
                      float* __restrict__ out) {
    __shared__ float s[32 * 65];

    const int bid   = blockIdx.x;         // 8192 blocks
    const int strip = bid & 3;            // 4 strips of 32 w-blocks
    const int h     = (bid >> 2) & 127;   // block row
    const int b     = bid >> 9;           // batch

    const int tx   = threadIdx.x;
    const int wblk = tx & 31;             // which 8x8 block in the strip
    const int r    = tx >> 5;             // stage1: row index; stage2: l index

    // ---- stage 1: load row r, row DCT, write to smem ----
    const float* ip = img + ((size_t)b << 20)
                          + (size_t)(h * 8 + r) * 1024
                          + (strip * 32 + wblk) * 8;
    const float4 p0 = reinterpret_cast<const float4*>(ip)[0];
    const float4 p1 = reinterpret_cast<const float4*>(ip)[1];
    const float x[8] = {p0.x, p0.y, p0.z, p0.w, p1.x, p1.y, p1.z, p1.w};

#pragma unroll
    for (int l = 0; l < 8; l++) {
        float acc = dctc(l, 0) * x[0];
#pragma unroll
        for (int m = 1; m < 8; m++) acc = fmaf(dctc(l, m), x[m], acc);
        s[wblk * 65 + r * 8 + l] = acc;
    }

    __syncthreads();

    // ---- stage 2: gather column l, column DCT, quantize, store ----
    const int l = r;
    float a[8];
#pragma unroll
    for (int rr = 0; rr < 8; rr++) a[rr] = s[wblk * 65 + rr * 8 + l];

    float v[8];
#pragma unroll
    for (int k = 0; k < 8; k++) {
        float acc = dctc(k, 0) * a[0];
#pragma unroll
        for (int rr = 1; rr < 8; rr++) acc = fmaf(dctc(k, rr), a[rr], acc);
        v[k] = acc;
    }

    if (l == 0) v[0] -= 1024.0f;  // folded "-128" mean shift (DC only)

    const float q    = __ldg(qf + b);
    const float invf = (q < 50.0f) ? (q * 0.0002f)
                                   : (1.0f / (200.0f - 2.0f * q));

    // out[b, k*8+l, h, w0+wblk]: lanes (wblk) contiguous -> 128B coalesced STG
    float* op = out + ((size_t)b << 20) + (size_t)l * 16384
                    + h * 128 + strip * 32 + wblk;
#pragma unroll
    for (int k = 0; k < 8; k++)
        op[(size_t)k * 131072] = (v[k] * invq(k, l)) * invf;
}

extern "C" void kernel_launch(void* const* d_in, const int* in_sizes, int n_in,
                              void* d_out, int out_size) {
    const float* img = (const float*)d_in[0];   // [16,1,1024,1024] fp32
    const float* qf  = (const float*)d_in[1];   // [16] fp32
    float* out = (float*)d_out;                 // [16,64,128,128] fp32

    // 16 batches * 128 block-rows * 4 strips = 8192 CTAs of 256 threads
    jpeg_dctq_kernel<<<8192, 256>>>(img, qf, out);
}

// round 4
// speedup vs baseline: 3.1042x; 3.1042x over previous
#include <cuda_runtime.h>
#include <cstddef>

// ---------------------------------------------------------------------------
// Compile-time DCT coefficients (always called with literal args -> fold to
// FP32 immediates; FFMA-imm form has rt_SMSP=1 on sm_103a).
// ---------------------------------------------------------------------------
__device__ __host__ constexpr float cospi16(int m) {
    constexpr float t[9] = {
        1.0f,
        0.9807852804032304f, 0.9238795325112867f, 0.8314696123025452f,
        0.7071067811865476f, 0.5555702330196022f, 0.3826834323650898f,
        0.1950903220161283f, 0.0f};
    m %= 32; if (m < 0) m += 32;
    if (m > 16) m = 32 - m;
    return (m <= 8) ? t[m] : -t[16 - m];
}

// C[k][n] = f_k * cos(pi*(2n+1)*k/16)
__device__ __host__ constexpr float dctc(int k, int n) {
    return (k == 0 ? 0.3535533905932738f : 0.5f) * cospi16((2 * n + 1) * k);
}

// Pre-divided inverse quant table: 100 / lum[k][l], runtime-indexable via LDC.
// (R2 lesson: constexpr lookup with a RUNTIME index generates per-thread
// select-chains + FP divides — a ~7x instruction explosion.)
__constant__ float INVQ[64] = {
    100.f/16.f, 100.f/11.f, 100.f/10.f, 100.f/16.f, 100.f/24.f, 100.f/40.f,  100.f/51.f,  100.f/61.f,
    100.f/12.f, 100.f/12.f, 100.f/14.f, 100.f/19.f, 100.f/26.f, 100.f/58.f,  100.f/60.f,  100.f/55.f,
    100.f/14.f, 100.f/13.f, 100.f/16.f, 100.f/24.f, 100.f/40.f, 100.f/57.f,  100.f/69.f,  100.f/56.f,
    100.f/14.f, 100.f/17.f, 100.f/22.f, 100.f/29.f, 100.f/51.f, 100.f/87.f,  100.f/80.f,  100.f/62.f,
    100.f/18.f, 100.f/22.f, 100.f/37.f, 100.f/56.f, 100.f/68.f, 100.f/109.f, 100.f/103.f, 100.f/77.f,
    100.f/24.f, 100.f/36.f, 100.f/55.f, 100.f/64.f, 100.f/81.f, 100.f/104.f, 100.f/113.f, 100.f/92.f,
    100.f/49.f, 100.f/64.f, 100.f/78.f, 100.f/87.f, 100.f/103.f,100.f/121.f, 100.f/120.f, 100.f/101.f,
    100.f/72.f, 100.f/92.f, 100.f/95.f, 100.f/98.f, 100.f/112.f,100.f/100.f, 100.f/103.f, 100.f/99.f};

// Fast 8-point orthonormal DCT-II using even/odd symmetry C[k][n] = ±C[k][7-n].
// 8 ADD/SUB + 32 FFMA-imm (vs 64 for the naive form). All coeffs literal.
__device__ __forceinline__ void dct8(const float x[8], float y[8]) {
    float e[4], o[4];
#pragma unroll
    for (int n = 0; n < 4; n++) { e[n] = x[n] + x[7 - n]; o[n] = x[n] - x[7 - n]; }
#pragma unroll
    for (int k = 0; k < 8; k += 2) {          // even rows: symmetric
        float acc = dctc(k, 0) * e[0];
#pragma unroll
        for (int n = 1; n < 4; n++) acc = fmaf(dctc(k, n), e[n], acc);
        y[k] = acc;
    }
#pragma unroll
    for (int k = 1; k < 8; k += 2) {          // odd rows: antisymmetric
        float acc = dctc(k, 0) * o[0];
#pragma unroll
        for (int n = 1; n < 4; n++) acc = fmaf(dctc(k, n), o[n], acc);
        y[k] = acc;
    }
}

// ---------------------------------------------------------------------------
// 8 threads per 8x8 block; 256-thread CTA handles a strip of 32 blocks.
// Stage 1: thread (r, wblk) loads row r (2x LDG.128, warp covers 512B
//          contiguous), row-DCTs it, writes to smem (stride 65, conflict-free).
// Stage 2: thread (l, wblk) gathers column l (conflict-free), column-DCTs,
//          quantizes via LDC + FFMA, stores 8 coalesced STG.32.
// The reference's (x-128) shift only moves the 2D DC coef by 128*8=1024.
// ---------------------------------------------------------------------------
__global__ __launch_bounds__(256)
void jpeg_dctq_kernel(const float* __restrict__ img,
                      const float* __restrict__ qf,
                      float* __restrict__ out) {
    __shared__ float s[32 * 65];

    const int bid   = blockIdx.x;         // 8192 CTAs
    const int strip = bid & 3;
    const int h     = (bid >> 2) & 127;
    const int b     = bid >> 9;

    const int tx   = threadIdx.x;
    const int wblk = tx & 31;
    const int r    = tx >> 5;             // stage1 row / stage2 l

    // ---- stage 1: load + row DCT ----
    const float* ip = img + ((size_t)b << 20)
                          + (size_t)(h * 8 + r) * 1024
                          + (strip * 32 + wblk) * 8;
    const float4 p0 = reinterpret_cast<const float4*>(ip)[0];
    const float4 p1 = reinterpret_cast<const float4*>(ip)[1];
    const float x[8] = {p0.x, p0.y, p0.z, p0.w, p1.x, p1.y, p1.z, p1.w};

    float y[8];
    dct8(x, y);
#pragma unroll
    for (int l = 0; l < 8; l++) s[wblk * 65 + r * 8 + l] = y[l];

    __syncthreads();

    // ---- stage 2: gather column l, column DCT ----
    const int l = r;
    float a[8];
#pragma unroll
    for (int rr = 0; rr < 8; rr++) a[rr] = s[wblk * 65 + rr * 8 + l];

    float v[8];
    dct8(a, v);

    if (l == 0) v[0] -= 1024.0f;          // folded "-128" mean shift (DC only)

    const float q    = __ldg(qf + b);
    const float invf = (q < 50.0f) ? (q * 0.0002f)
                                   : (1.0f / (200.0f - 2.0f * q));

    // out[b, k*8+l, h, w]: lanes (wblk) contiguous -> 128B coalesced STG.32
    float* op = out + ((size_t)b << 20) + (size_t)l * 16384
                    + h * 128 + strip * 32 + wblk;
#pragma unroll
    for (int k = 0; k < 8; k++)
        op[(size_t)k * 131072] = v[k] * (INVQ[k * 8 + l] * invf);
}

extern "C" void kernel_launch(void* const* d_in, const int* in_sizes, int n_in,
                              void* d_out, int out_size) {
    const float* img = (const float*)d_in[0];   // [16,1,1024,1024] fp32
    const float* qf  = (const float*)d_in[1];   // [16] fp32
    float* out = (float*)d_out;                 // [16,64,128,128] fp32

    jpeg_dctq_kernel<<<8192, 256>>>(img, qf, out);
}